// round 17
// baseline (speedup 1.0000x reference)
#include <cuda_runtime.h>
#include <cuda_fp16.h>
#include <math.h>
#include <stdint.h>

// ---------------------------------------------------------------------------
// Problem constants
// ---------------------------------------------------------------------------
#define B_   64
#define S_   512
#define F_   512
#define HS_  1024
#define G3_  3072
#define M_   (B_ * S_)

// Persistent config: 32 gate-grouped n-tiles (96 cols) x 4 K-splits = 128 blocks
// Each block interleaves TWO independent 32-batch chains (bg0/bg1).
#define NTILES 32
#define KSPLIT 4
#define NBLK_P (NTILES * KSPLIT)     // 128
#define NTC    96                    // cols per tile (3 gates x 32 cc)
#define KPER   256                   // k per block
#define KC     32                    // k chunk
#define NCH    (KPER / KC)           // 8
#define NTHR   384                   // 12 warps

// smem: W 8 chunks x 6KB = 49152; A: 2 chains x 8 chunks x 2KB = 32768
#define SMW_CH   6144
#define SMA_OFF  49152
#define SMA_CHN  16384               // per-chain A region
#define SMA_CH   2048                // per-chunk (32 rows x 64B)
#define SMEM_TOT 81920

// ---------------------------------------------------------------------------
// Device scratch
// ---------------------------------------------------------------------------
__device__ float g_gx[(size_t)M_ * G3_];
// gh partials: [parity][bg][kh][32 batches x G3], batch-local rows
__device__ float g_ghp[2][2][KSPLIT][32 * G3_];
__device__ __half g_hh16[4][B_ * HS_];              // h fp16 (4-deep)
__device__ __half g_wt16[(size_t)G3_ * HS_];        // W_hh^T fp16, PERMUTED rows
__device__ __half g_wi16[(size_t)G3_ * F_];         // W_ih^T fp16 [3072][512]
__device__ __half g_x16[(size_t)M_ * F_];           // x fp16 [32768][512]

// Monotone counters per chain, prezeroed each launch.
__device__ unsigned g_pdone[2][S_ * NTILES];                      // ->4
__device__ __align__(16) unsigned g_tdone[2][(S_ + 1) * NTILES];  // ->4

// ---------------------------------------------------------------------------
// PTX helpers (compute_80-level — target is compute_103 non-'a')
// ---------------------------------------------------------------------------
__device__ __forceinline__ uint32_t s2u(const void* p) {
    uint32_t r;
    asm("{ .reg .u64 t; cvta.to.shared.u64 t, %1; cvt.u32.u64 %0, t; }"
        : "=r"(r) : "l"(p));
    return r;
}
__device__ __forceinline__ void cpasync16(uint32_t dst, const void* src) {
    asm volatile("cp.async.cg.shared.global [%0], [%1], 16;"
                 :: "r"(dst), "l"(src));
}
__device__ __forceinline__ void ldsm4(uint32_t* r, uint32_t addr) {
    asm volatile("ldmatrix.sync.aligned.m8n8.x4.shared.b16 {%0,%1,%2,%3}, [%4];"
                 : "=r"(r[0]), "=r"(r[1]), "=r"(r[2]), "=r"(r[3]) : "r"(addr));
}
__device__ __forceinline__ void mma_f16(float* c, const uint32_t* a,
                                        const uint32_t* b) {
    asm volatile(
        "mma.sync.aligned.m16n8k16.row.col.f32.f16.f16.f32 "
        "{%0,%1,%2,%3}, {%4,%5,%6,%7}, {%8,%9}, {%0,%1,%2,%3};"
        : "+f"(c[0]), "+f"(c[1]), "+f"(c[2]), "+f"(c[3])
        : "r"(a[0]), "r"(a[1]), "r"(a[2]), "r"(a[3]), "r"(b[0]), "r"(b[1]));
}
__device__ __forceinline__ float ldcg(const float* p) {
    float v;
    asm volatile("ld.global.cg.f32 %0, [%1];" : "=f"(v) : "l"(p));
    return v;
}
__device__ __forceinline__ void redadd(unsigned* p, unsigned v) {
    asm volatile("red.global.add.u32 [%0], %1;" :: "l"(p), "r"(v) : "memory");
}
// Fast activations
__device__ __forceinline__ float fsig(float x) {
    return __fdividef(1.0f, 1.0f + __expf(-x));
}
__device__ __forceinline__ float ftanh(float x) {
    return 1.0f - __fdividef(2.0f, __expf(2.0f * x) + 1.0f);
}
// 16B-granule swizzle for 64B rows: conflict-free 8-row ldmatrix phases.
__device__ __forceinline__ uint32_t swz(int r, int q) {
    return (uint32_t)(r * 64 + ((q ^ ((r >> 1) & 3)) << 4));
}
#define WAITG(n) asm volatile("cp.async.wait_group %0;" :: "n"(n))

// ---------------------------------------------------------------------------
// Fused prep kernel
// ---------------------------------------------------------------------------
__global__ void prep_all_kernel(const float* __restrict__ x,
                                const float* __restrict__ whh,
                                const float* __restrict__ wih) {
    size_t i = (size_t)blockIdx.x * blockDim.x + threadIdx.x;

    g_x16[i] = __float2half(x[i]);

    if (i < (size_t)G3_ * HS_) {
        int k = (int)(i / G3_), n = (int)(i % G3_);
        int gate = n / HS_, cc = n % HS_;
        int n_new = (cc >> 5) * NTC + gate * 32 + (cc & 31);
        g_wt16[(size_t)n_new * HS_ + k] = __float2half(whh[i]);
    }
    if (i < (size_t)G3_ * F_) {
        int k = (int)(i / G3_), n = (int)(i % G3_);
        g_wi16[(size_t)n * F_ + k] = __float2half(wih[i]);
    }
    if (i < (size_t)(B_ * HS_)) g_hh16[0][i] = __float2half(0.0f);
    if (i < (size_t)(S_ * NTILES)) {
        g_pdone[0][i] = 0u; g_pdone[1][i] = 0u;
    }
    if (i < (size_t)((S_ + 1) * NTILES)) {
        g_tdone[0][i] = 0u; g_tdone[1][i] = 0u;
    }
}

// ---------------------------------------------------------------------------
// Phase 1 GEMM (validated, unchanged): gx = x16 @ Wih16^T (+bias).
// ---------------------------------------------------------------------------
__global__ void __launch_bounds__(128) mma_gemm16_kernel(
    const __half* __restrict__ A, const __half* __restrict__ Bw,
    float* __restrict__ out, const float* __restrict__ bias, int K)
{
    __shared__ __align__(16) uint8_t smem_raw[2][12288];
    const int tid = threadIdx.x, lid = tid & 31, wid = tid >> 5;
    const int wm = wid & 1, wn = wid >> 1;
    const int m0 = blockIdx.y * 64, n0 = blockIdx.x * 128;
    const uint32_t sm0 = s2u(smem_raw[0]), sm1 = s2u(smem_raw[1]);

    float acc[2][8][4];
#pragma unroll
    for (int i = 0; i < 2; i++)
#pragma unroll
        for (int j = 0; j < 8; j++)
#pragma unroll
            for (int v = 0; v < 4; v++) acc[i][j][v] = 0.0f;

    const int NC = K >> 5;
    auto load_chunk = [&](uint32_t sb, int k0) {
#pragma unroll
        for (int i = 0; i < 2; i++) {
            int cid = tid + i * 128;
            int r = cid >> 2, q = cid & 3;
            cpasync16(sb + swz(r, q), A + (size_t)(m0 + r) * K + k0 + q * 8);
        }
#pragma unroll
        for (int i = 0; i < 4; i++) {
            int cid = tid + i * 128;
            int r = cid >> 2, q = cid & 3;
            cpasync16(sb + 4096 + swz(r, q), Bw + (size_t)(n0 + r) * K + k0 + q * 8);
        }
        asm volatile("cp.async.commit_group;");
    };

    load_chunk(sm0, 0);
    for (int c = 0; c < NC; c++) {
        if (c + 1 < NC) {
            load_chunk(((c + 1) & 1) ? sm1 : sm0, (c + 1) * KC);
            asm volatile("cp.async.wait_group 1;");
        } else {
            asm volatile("cp.async.wait_group 0;");
        }
        __syncthreads();
        const uint32_t sb = (c & 1) ? sm1 : sm0;
#pragma unroll
        for (int kk = 0; kk < 2; kk++) {
            const int qq = kk * 2 + (lid >> 4);
            uint32_t afr[2][4];
#pragma unroll
            for (int i = 0; i < 2; i++) {
                int r = wm * 32 + i * 16 + (lid & 15);
                ldsm4(afr[i], sb + swz(r, qq));
            }
            uint32_t bfr[8][2];
#pragma unroll
            for (int jj = 0; jj < 4; jj++) {
                int r = wn * 64 + jj * 16 + (lid & 15);
                uint32_t t4[4];
                ldsm4(t4, sb + 4096 + swz(r, qq));
                bfr[2 * jj][0] = t4[0]; bfr[2 * jj][1] = t4[2];
                bfr[2 * jj + 1][0] = t4[1]; bfr[2 * jj + 1][1] = t4[3];
            }
#pragma unroll
            for (int i = 0; i < 2; i++)
#pragma unroll
                for (int j = 0; j < 8; j++)
                    mma_f16(acc[i][j], afr[i], bfr[j]);
        }
        __syncthreads();
    }
#pragma unroll
    for (int i = 0; i < 2; i++) {
        int m = m0 + wm * 32 + 16 * i + (lid >> 2);
#pragma unroll
        for (int j = 0; j < 8; j++) {
            int n = n0 + wn * 64 + 8 * j + 2 * (lid & 3);
            float b0 = bias[n], b1 = bias[n + 1];
            *(float2*)(out + (size_t)m * G3_ + n) =
                make_float2(acc[i][j][0] + b0, acc[i][j][1] + b1);
            *(float2*)(out + (size_t)(m + 8) * G3_ + n) =
                make_float2(acc[i][j][2] + b0, acc[i][j][3] + b1);
        }
    }
}

// ---------------------------------------------------------------------------
// Persistent recurrence: two interleaved 32-batch chains per block.
// 12 warps as 2m x 6n, warp tile 16m x 16n, M=32 per chain.
// Per step: poll0/A0, poll1/A1 (in flight), GEMM0->pdone0->pw0->pub0,
// GEMM1->pdone1->pw1->pub1. W smem shared by both chains.
// ---------------------------------------------------------------------------
__global__ void __launch_bounds__(NTHR) gru_persist_kernel(
    float* __restrict__ out, float* __restrict__ lastdst)
{
    extern __shared__ __align__(16) uint8_t smem[];
    const uint32_t wbase = s2u(smem);
    const uint32_t abase = wbase + SMA_OFF;

    const int tid = threadIdx.x, lid = tid & 31, wid = tid >> 5;
    const int wm = wid & 1;            // 0..1 (m halves of 32)
    const int wn = wid >> 1;           // 0..5 (n groups of 16)
    const int tile = blockIdx.x % NTILES;     // 0..31
    const int kh   = blockIdx.x / NTILES;     // 0..3
    const int n0   = tile * NTC;
    const int kbase = kh * KPER;

    // ---- one-time: W16 tile load (3072 granules, 8/thread) ----
#pragma unroll
    for (int i = 0; i < 8; i++) {
        int gid = tid + i * NTHR;
        int c   = gid / 384;
        int g   = gid % 384;
        int r   = g >> 2, q = g & 3;
        cpasync16(wbase + c * SMW_CH + swz(r, q),
                  g_wt16 + (size_t)(n0 + r) * HS_ + kbase + c * KC + q * 8);
    }
    asm volatile("cp.async.commit_group;");
    asm volatile("cp.async.wait_group 0;");
    __syncthreads();

    // pointwise mapping (fixed per thread, per chain): tid<256 active
    const int bl  = tid >> 5;          // 0..7 local batch
    const int ccl = tid & 31;
    const int cc  = tile * 32 + ccl;
    float hreg[2] = {0.0f, 0.0f};      // per-chain register-carried h

    // producer-poll helper (8 counters == 4, two v4 volatile loads)
    auto pollwait = [&](const unsigned* p) {
        while (true) {
            unsigned a0, a1, a2, a3, c0, c1, c2, c3;
            asm volatile("ld.volatile.global.v4.u32 {%0,%1,%2,%3}, [%4];"
                         : "=r"(a0), "=r"(a1), "=r"(a2), "=r"(a3) : "l"(p));
            asm volatile("ld.volatile.global.v4.u32 {%0,%1,%2,%3}, [%4];"
                         : "=r"(c0), "=r"(c1), "=r"(c2), "=r"(c3) : "l"(p + 4));
            if ((a0 & a1 & a2 & a3 & c0 & c1 & c2 & c3) == 4u &&
                (a0 | a1 | a2 | a3 | c0 | c1 | c2 | c3) == 4u)
                break;
        }
    };

    // per-chunk compute: 16m x 96n, chain bg, chunk c
    auto comp = [&](int bg, int c, float (*acc)[4]) {
        const uint32_t sbA = abase + bg * SMA_CHN + c * SMA_CH;
        const uint32_t sbW = wbase + c * SMW_CH;
#pragma unroll
        for (int kk = 0; kk < 2; kk++) {
            const int qq = kk * 2 + (lid >> 4);
            uint32_t afr[4];
            ldsm4(afr, sbA + swz(wm * 16 + (lid & 15), qq));
            uint32_t bfr[2][2];
            {
                int r = wn * 16 + (lid & 15);
                uint32_t t4[4];
                ldsm4(t4, sbW + swz(r, qq));
                bfr[0][0] = t4[0]; bfr[0][1] = t4[2];
                bfr[1][0] = t4[1]; bfr[1][1] = t4[3];
            }
            mma_f16(acc[0], afr, bfr[0]);
            mma_f16(acc[1], afr, bfr[1]);
        }
    };

    for (int t = 0; t < S_; t++) {
        const __half* __restrict__ Ah0 = g_hh16[t & 3] + kbase;            // rows 0..31
        const __half* __restrict__ Ah1 = g_hh16[t & 3] + 32 * HS_ + kbase; // rows 32..63

        // ---- chain0 poll + A0 issue (8 commit groups) ----
        if (t > 0) {
            if (tid == 0) pollwait(&g_tdone[0][t * NTILES + 8 * kh]);
            __syncthreads();
        }
#pragma unroll
        for (int c = 0; c < NCH; c++) {
            if (tid < 128) {
                int r = tid >> 2, q = tid & 3;
                cpasync16(abase + c * SMA_CH + swz(r, q),
                          Ah0 + (size_t)r * HS_ + c * KC + q * 8);
            }
            asm volatile("cp.async.commit_group;");
        }

        // ---- chain1 poll + A1 issue (8 commit groups) ----
        if (t > 0) {
            if (tid == 0) pollwait(&g_tdone[1][t * NTILES + 8 * kh]);
            __syncthreads();
        }
#pragma unroll
        for (int c = 0; c < NCH; c++) {
            if (tid < 128) {
                int r = tid >> 2, q = tid & 3;
                cpasync16(abase + SMA_CHN + c * SMA_CH + swz(r, q),
                          Ah1 + (size_t)r * HS_ + c * KC + q * 8);
            }
            asm volatile("cp.async.commit_group;");
        }

        // ---- gx registers for both chains (off-chain) ----
        float gxv[2][3];
#pragma unroll
        for (int bg = 0; bg < 2; bg++) {
            if (tid < 256) {
                int b = bg * 32 + kh * 8 + bl;
                const float* gxp = g_gx + ((size_t)b * S_ + t) * G3_;
                gxv[bg][0] = gxp[cc];
                gxv[bg][1] = gxp[HS_ + cc];
                gxv[bg][2] = gxp[2 * HS_ + cc];
            } else {
                gxv[bg][0] = gxv[bg][1] = gxv[bg][2] = 0.0f;
            }
        }

        // ================= chain segments =================
#pragma unroll
        for (int bg = 0; bg < 2; bg++) {
            float acc[2][4];
#pragma unroll
            for (int j = 0; j < 2; j++)
#pragma unroll
                for (int v = 0; v < 4; v++) acc[j][v] = 0.0f;

            // quarter-granularity waits; group counts account for both chains
            if (bg == 0) {
                WAITG(14); __syncthreads(); comp(0, 0, acc); comp(0, 1, acc);
                WAITG(12); __syncthreads(); comp(0, 2, acc); comp(0, 3, acc);
                WAITG(10); __syncthreads(); comp(0, 4, acc); comp(0, 5, acc);
                WAITG(8);  __syncthreads(); comp(0, 6, acc); comp(0, 7, acc);
            } else {
                WAITG(6); __syncthreads(); comp(1, 0, acc); comp(1, 1, acc);
                WAITG(4); __syncthreads(); comp(1, 2, acc); comp(1, 3, acc);
                WAITG(2); __syncthreads(); comp(1, 4, acc); comp(1, 5, acc);
                WAITG(0); __syncthreads(); comp(1, 6, acc); comp(1, 7, acc);
            }

            // store partial gh tile (batch-local rows 0..31)
            float* __restrict__ ghdst = g_ghp[t & 1][bg][kh];
            {
                int m = wm * 16 + (lid >> 2);
#pragma unroll
                for (int j = 0; j < 2; j++) {
                    int nc = n0 + wn * 16 + 8 * j + 2 * (lid & 3);
                    *(float2*)(ghdst + (size_t)m * G3_ + nc) =
                        make_float2(acc[j][0], acc[j][1]);
                    *(float2*)(ghdst + (size_t)(m + 8) * G3_ + nc) =
                        make_float2(acc[j][2], acc[j][3]);
                }
            }

            // tile-local 4-way sync (per chain)
            __threadfence();
            __syncthreads();
            if (tid == 0) {
                unsigned old = atomicAdd(&g_pdone[bg][t * NTILES + tile], 1u);
                if (old != 3u) {
                    while (*((volatile unsigned*)&g_pdone[bg][t * NTILES + tile])
                           != 4u) { }
                }
            }
            __syncthreads();

            // pointwise for own slice: 8 b x 32 cc = 256 elems
            const int tp = t & 1;
            const int o  = (t + 1) & 3;
            float hn_sv = 0.0f;
            int   hidx_sv = -1, b_sv = 0;
            if (tid < 256) {
                int b    = bg * 32 + kh * 8 + bl;
                int mrow = kh * 8 + bl;           // batch-local row in ghp
                size_t base = (size_t)mrow * G3_ + n0 + ccl;
                const float* p0 = g_ghp[tp][bg][0];
                const float* p1 = g_ghp[tp][bg][1];
                const float* p2 = g_ghp[tp][bg][2];
                const float* p3 = g_ghp[tp][bg][3];
                float ghz = ldcg(p0 + base)      + ldcg(p1 + base)
                          + ldcg(p2 + base)      + ldcg(p3 + base);
                float ghr = ldcg(p0 + base + 32) + ldcg(p1 + base + 32)
                          + ldcg(p2 + base + 32) + ldcg(p3 + base + 32);
                float ghe = ldcg(p0 + base + 64) + ldcg(p1 + base + 64)
                          + ldcg(p2 + base + 64) + ldcg(p3 + base + 64);
                float z   = fsig(gxv[bg][0] + ghz);
                float r   = fsig(gxv[bg][1] + ghr);
                float eta = ftanh(gxv[bg][2] + r * ftanh(ghe));
                float hn  = z * hreg[bg] + (1.0f - z) * eta;
                hreg[bg] = hn;
                int hidx = b * HS_ + cc;
                g_hh16[o][hidx] = __float2half(hn);   // consumers need only this
                hn_sv = hn; hidx_sv = hidx; b_sv = b;
            }

            // publish h(t+1) cols for this (chain, tile)
            __threadfence();
            __syncthreads();
            if (tid == 0) redadd(&g_tdone[bg][(t + 1) * NTILES + tile], 1u);

            // off-critical-path writes
            if (hidx_sv >= 0) {
                out[((size_t)b_sv * S_ + t) * HS_ + cc] = hn_sv;
                if (lastdst && t == S_ - 1) lastdst[hidx_sv] = hn_sv;
            }
        }
    }
}

// ---------------------------------------------------------------------------
// Host launch — 3 graph nodes.
// ---------------------------------------------------------------------------
extern "C" void kernel_launch(void* const* d_in, const int* in_sizes, int n_in,
                              void* d_out, int out_size) {
    const float* x    = (const float*)d_in[0];
    const float* wih  = (const float*)d_in[1];
    const float* whh  = (const float*)d_in[2];
    const float* bias = (const float*)d_in[3];
    float* out = (float*)d_out;

    void *p_x16, *p_wi16, *p_gx;
    cudaGetSymbolAddress(&p_x16,  g_x16);
    cudaGetSymbolAddress(&p_wi16, g_wi16);
    cudaGetSymbolAddress(&p_gx,   g_gx);

    cudaFuncSetAttribute(gru_persist_kernel,
                         cudaFuncAttributeMaxDynamicSharedMemorySize, SMEM_TOT);

    prep_all_kernel<<<16384, 1024>>>(x, whh, wih);

    mma_gemm16_kernel<<<dim3(24, M_ / 64), 128>>>(
        (const __half*)p_x16, (const __half*)p_wi16,
        (float*)p_gx, bias, F_);

    const long long seq_elems = (long long)B_ * S_ * HS_;
    float* lastdst = ((long long)out_size >= seq_elems + (long long)B_ * HS_)
                         ? out + seq_elems : nullptr;

    gru_persist_kernel<<<NBLK_P, NTHR, SMEM_TOT>>>(out, lastdst);
}